// round 16
// baseline (speedup 1.0000x reference)
#include <cuda_runtime.h>
#include <cuda_fp16.h>
#include <cstdint>

#define BDIM 4
#define SEQ  2048
#define DM   1024
#define NH   16
#define HD   64
#define BH   (BDIM*NH)     // 64
#define MTOT (BDIM*SEQ)    // 8192
#define LOG2E 1.4426950408889634f
#define QSCALE (0.125f * LOG2E)

// Static scratch
__device__ uint32_t g_wa[(DM/2) * (3*DM)];      // W_attn, k-pair packed half2
__device__ uint32_t g_wp[(DM/2) * DM];          // W_proj,  k-pair packed half2
__device__ __half   g_qh[BH * SEQ * HD];        // q (pre-scaled by QSCALE)
__device__ __half   g_kh[BH * SEQ * HD];
__device__ __half   g_vh[BH * SEQ * HD];
__device__ __half   g_ah[MTOT * DM];            // merged attn out, fp16

__device__ __forceinline__ float fexp2(float x) {
    float y;
    asm("ex2.approx.ftz.f32 %0, %1;" : "=f"(y) : "f"(x));
    return y;
}

__device__ __forceinline__ void mma_f16(float* d, const uint32_t* a, const uint32_t* b) {
    asm volatile(
        "mma.sync.aligned.m16n8k16.row.col.f32.f16.f16.f32 "
        "{%0,%1,%2,%3}, {%4,%5,%6,%7}, {%8,%9}, {%0,%1,%2,%3};"
        : "+f"(d[0]), "+f"(d[1]), "+f"(d[2]), "+f"(d[3])
        : "r"(a[0]), "r"(a[1]), "r"(a[2]), "r"(a[3]), "r"(b[0]), "r"(b[1]));
}

__device__ __forceinline__ uint32_t h2u(__half2 h) { return *reinterpret_cast<uint32_t*>(&h); }

// ---------------------------------------------------------------------------
// One-time weight packing kernels (x conversion fused into GEMM1 staging)
// ---------------------------------------------------------------------------
__global__ void pack_wa_k(const float* __restrict__ W) {
    const int ND = 3 * DM;
    int idx = blockIdx.x * 256 + threadIdx.x;        // over (DM/2)*ND
    int kp = idx / ND, n = idx - kp * ND;
    g_wa[idx] = h2u(__floats2half2_rn(W[(2*kp)*ND + n], W[(2*kp+1)*ND + n]));
}

__global__ void pack_wp_k(const float* __restrict__ W) {
    const int ND = DM;
    int idx = blockIdx.x * 256 + threadIdx.x;        // over (DM/2)*ND
    int kp = idx / ND, n = idx - kp * ND;
    g_wp[idx] = h2u(__floats2half2_rn(W[(2*kp)*ND + n], W[(2*kp+1)*ND + n]));
}

// ---------------------------------------------------------------------------
// FP16 GEMM (m16n8k16, fp32 accum): C[M,N] = A @ B + bias
// 128 threads, 4 warps in 2x2, warp tile 64x64, BM=BN=128, BK=32.
// ASEL: 0 = fp32 x (converted at staging), 1 = g_ah fp16.
// BSEL: 0 = g_wa, 1 = g_wp.
// EPI: 0 = fp32 store to C.  1 = scatter fp16 into g_qh/g_kh/g_vh (q scaled).
// ---------------------------------------------------------------------------
template<int M, int N, int K, int EPI, int ASEL, int BSEL>
__global__ __launch_bounds__(128) void gemm_h(const float* __restrict__ Axf,
                                              const float* __restrict__ bias,
                                              float* __restrict__ C)
{
    constexpr int BK  = 32;
    constexpr int ASU = 20;    // uints per A row (16 data + 4 pad)
    constexpr int BSU = 136;   // uints per B kp-row (128 + 8 pad)
    __shared__ uint32_t As[128 * ASU];
    __shared__ uint32_t Bs[16 * BSU];

    const uint32_t* Bp = (BSEL == 0) ? g_wa : g_wp;

    const int t    = threadIdx.x;
    const int warp = t >> 5;
    const int lane = t & 31;
    const int wm   = (warp >> 1) * 64;
    const int wn   = (warp & 1) * 64;
    const int g    = lane >> 2;
    const int c    = lane & 3;
    const int row0 = blockIdx.y * 128;
    const int col0 = blockIdx.x * 128;

    float acc[4][8][4];
    #pragma unroll
    for (int i = 0; i < 4; i++)
        #pragma unroll
        for (int j = 0; j < 8; j++)
            #pragma unroll
            for (int q = 0; q < 4; q++) acc[i][j][q] = 0.f;

    for (int k0 = 0; k0 < K; k0 += BK) {
        // stage A: 128 rows x 16 uints = 512 uint4
        uint4 av[4], bv[4];
        #pragma unroll
        for (int u = 0; u < 4; u++) {
            int idx = t + u * 128;
            int row = idx >> 2, q4 = idx & 3;
            if (ASEL == 0) {
                const float* src = &Axf[(size_t)(row0 + row) * K + k0 + q4 * 8];
                float4 f0 = *reinterpret_cast<const float4*>(src);
                float4 f1 = *reinterpret_cast<const float4*>(src + 4);
                av[u].x = h2u(__floats2half2_rn(f0.x, f0.y));
                av[u].y = h2u(__floats2half2_rn(f0.z, f0.w));
                av[u].z = h2u(__floats2half2_rn(f1.x, f1.y));
                av[u].w = h2u(__floats2half2_rn(f1.z, f1.w));
            } else {
                av[u] = *reinterpret_cast<const uint4*>(&g_ah[(size_t)(row0 + row) * K + k0 + q4 * 8]);
            }
        }
        // stage B: 16 kp-rows x 128 uints = 512 uint4
        #pragma unroll
        for (int u = 0; u < 4; u++) {
            int idx = t + u * 128;
            int kp = idx >> 5, n4 = idx & 31;
            bv[u] = *reinterpret_cast<const uint4*>(&Bp[(size_t)(k0 / 2 + kp) * N + col0 + n4 * 4]);
        }
        __syncthreads();
        #pragma unroll
        for (int u = 0; u < 4; u++) {
            int idx = t + u * 128;
            int row = idx >> 2, q4 = idx & 3;
            *reinterpret_cast<uint4*>(&As[row * ASU + q4 * 4]) = av[u];
        }
        #pragma unroll
        for (int u = 0; u < 4; u++) {
            int idx = t + u * 128;
            int kp = idx >> 5, n4 = idx & 31;
            *reinterpret_cast<uint4*>(&Bs[kp * BSU + n4 * 4]) = bv[u];
        }
        __syncthreads();

        #pragma unroll
        for (int s = 0; s < 2; s++) {           // two k16 steps per BK=32
            const int kb = s * 8;
            uint32_t af[4][4];
            #pragma unroll
            for (int i = 0; i < 4; i++) {
                const int r = wm + i * 16 + g;
                af[i][0] = As[r * ASU + kb + c];
                af[i][1] = As[(r + 8) * ASU + kb + c];
                af[i][2] = As[r * ASU + kb + c + 4];
                af[i][3] = As[(r + 8) * ASU + kb + c + 4];
            }
            #pragma unroll
            for (int j = 0; j < 8; j++) {
                const int col = wn + j * 8 + g;
                uint32_t bf[2];
                bf[0] = Bs[(kb + c) * BSU + col];
                bf[1] = Bs[(kb + c + 4) * BSU + col];
                #pragma unroll
                for (int i = 0; i < 4; i++)
                    mma_f16(acc[i][j], af[i], bf);
            }
        }
    }

    // Epilogue. frag: c0 (g,2c), c1 (g,2c+1), c2 (g+8,2c), c3 (g+8,2c+1)
    #pragma unroll
    for (int i = 0; i < 4; i++) {
        const int r_lo = row0 + wm + i * 16 + g;
        #pragma unroll
        for (int j = 0; j < 8; j++) {
            const int cb = col0 + wn + j * 8 + c * 2;
            float v00 = acc[i][j][0] + bias[cb];
            float v01 = acc[i][j][1] + bias[cb + 1];
            float v10 = acc[i][j][2] + bias[cb];
            float v11 = acc[i][j][3] + bias[cb + 1];
            if (EPI == 0) {
                *reinterpret_cast<float2*>(&C[(size_t)r_lo * N + cb])       = make_float2(v00, v01);
                *reinterpret_cast<float2*>(&C[(size_t)(r_lo + 8) * N + cb]) = make_float2(v10, v11);
            } else {
                const int which = cb >> 10;        // 0:q 1:k 2:v
                const int dd    = cb & 1023;
                const int h     = dd >> 6;
                const int d     = dd & 63;
                __half* dst = (which == 0) ? g_qh : (which == 1) ? g_kh : g_vh;
                if (which == 0) { v00 *= QSCALE; v01 *= QSCALE; v10 *= QSCALE; v11 *= QSCALE; }
                #pragma unroll
                for (int rr = 0; rr < 2; rr++) {
                    const int r = r_lo + rr * 8;
                    const int b = r >> 11;
                    const int s = r & 2047;
                    const size_t di = (((size_t)(b * NH + h) * SEQ) + s) * HD + d;
                    __half2 hh = __floats2half2_rn(rr ? v10 : v00, rr ? v11 : v01);
                    *reinterpret_cast<uint32_t*>(&dst[di]) = h2u(hh);
                }
            }
        }
    }
}

// ---------------------------------------------------------------------------
// FP16 tensor-core flash attention (m16n8k16), software-pipelined staging:
// tile kt+1's K/V/mask are prefetched into registers while tile kt computes.
// ---------------------------------------------------------------------------
#define KSU 36   // Ks row stride (uints): conflict-free
#define VSU 72   // Vs kp-row stride: conflict-free
#define PSU 36   // Ps row stride

__global__ __launch_bounds__(128, 2) void attn_h(const float* __restrict__ amask)
{
    __shared__ uint32_t Ks[64 * KSU];    // [key][hd_pair]
    __shared__ uint32_t Vs[32 * VSU];    // [key_pair][hd]
    __shared__ uint32_t Ps[128 * PSU];   // [q_row][key_pair]
    __shared__ float    Ms[64];          // mask (scaled by log2e)

    const int bh   = blockIdx.y;
    const int qt   = blockIdx.x;
    const int b    = bh >> 4;
    const int h    = bh & 15;
    const int q0   = qt * 128;
    const int t    = threadIdx.x;
    const int warp = t >> 5;
    const int lane = t & 31;
    const int g    = lane >> 2;
    const int c    = lane & 3;
    const int wm   = warp * 32;

    const uint32_t* Qu = reinterpret_cast<const uint32_t*>(g_qh) + (size_t)bh * SEQ * 32;
    const uint32_t* Ku = reinterpret_cast<const uint32_t*>(g_kh) + (size_t)bh * SEQ * 32;
    const uint32_t* Vu = reinterpret_cast<const uint32_t*>(g_vh) + (size_t)bh * SEQ * 32;

    constexpr float NEGL = -10000.f * LOG2E;

    // ---- Q fragments: straight from gmem (k-loop invariant) ----
    uint32_t Qr[2][4][4];
    #pragma unroll
    for (int i = 0; i < 2; i++) {
        const int r = q0 + wm + i * 16 + g;
        #pragma unroll
        for (int kk = 0; kk < 4; kk++) {
            Qr[i][kk][0] = Qu[r * 32 + kk * 8 + c];
            Qr[i][kk][1] = Qu[(r + 8) * 32 + kk * 8 + c];
            Qr[i][kk][2] = Qu[r * 32 + kk * 8 + c + 4];
            Qr[i][kk][3] = Qu[(r + 8) * 32 + kk * 8 + c + 4];
        }
    }

    // prefetch-register staging state
    uint4 kpre[4], vlo[2], vhi[2];
    float mpre = 0.f;
    const int krow = t >> 3;          // K: row this thread stages (u*... see below)
    const int kq4  = t & 7;
    const int vkp  = t >> 3;          // V: key-pair base
    const int vub  = t & 7;

    auto PREFETCH = [&](int k0) {
        #pragma unroll
        for (int u = 0; u < 4; u++)
            kpre[u] = *reinterpret_cast<const uint4*>(&Ku[(size_t)(k0 + krow + u * 16) * 32 + kq4 * 4]);
        #pragma unroll
        for (int u = 0; u < 2; u++) {
            vlo[u] = *reinterpret_cast<const uint4*>(&Vu[(size_t)(k0 + 2 * (vkp + u * 16))     * 32 + vub * 4]);
            vhi[u] = *reinterpret_cast<const uint4*>(&Vu[(size_t)(k0 + 2 * (vkp + u * 16) + 1) * 32 + vub * 4]);
        }
        if (t < 64) mpre = amask[b * SEQ + k0 + t];
    };

    float oacc[2][8][4];
    #pragma unroll
    for (int i = 0; i < 2; i++)
        #pragma unroll
        for (int j = 0; j < 8; j++)
            #pragma unroll
            for (int q = 0; q < 4; q++) oacc[i][j][q] = 0.f;
    float mv[2][2], lv[2][2];
    #pragma unroll
    for (int i = 0; i < 2; i++) {
        mv[i][0] = -1e30f; mv[i][1] = -1e30f;
        lv[i][0] = 0.f;    lv[i][1] = 0.f;
    }

    const int ktiles = 2 * qt + 2;
    PREFETCH(0);
    for (int kt = 0; kt < ktiles; kt++) {
        const int k0 = kt * 64;
        __syncthreads();
        // ---- commit prefetched tile to smem ----
        #pragma unroll
        for (int u = 0; u < 4; u++)
            *reinterpret_cast<uint4*>(&Ks[(krow + u * 16) * KSU + kq4 * 4]) = kpre[u];
        #pragma unroll
        for (int u = 0; u < 2; u++) {
            uint4 lo = vlo[u], hi = vhi[u];
            uint4 o0, o1;
            o0.x = __byte_perm(lo.x, hi.x, 0x5410); o0.y = __byte_perm(lo.x, hi.x, 0x7632);
            o0.z = __byte_perm(lo.y, hi.y, 0x5410); o0.w = __byte_perm(lo.y, hi.y, 0x7632);
            o1.x = __byte_perm(lo.z, hi.z, 0x5410); o1.y = __byte_perm(lo.z, hi.z, 0x7632);
            o1.z = __byte_perm(lo.w, hi.w, 0x5410); o1.w = __byte_perm(lo.w, hi.w, 0x7632);
            *reinterpret_cast<uint4*>(&Vs[(vkp + u * 16) * VSU + vub * 8])     = o0;
            *reinterpret_cast<uint4*>(&Vs[(vkp + u * 16) * VSU + vub * 8 + 4]) = o1;
        }
        if (t < 64) Ms[t] = mpre * LOG2E;
        __syncthreads();

        // ---- prefetch next tile (overlaps with compute below) ----
        if (kt + 1 < ktiles) PREFETCH(k0 + 64);

        // ---- S = Q K^T ----
        float sacc[2][8][4];
        #pragma unroll
        for (int i = 0; i < 2; i++)
            #pragma unroll
            for (int j = 0; j < 8; j++)
                #pragma unroll
                for (int q = 0; q < 4; q++) sacc[i][j][q] = 0.f;

        #pragma unroll
        for (int kk = 0; kk < 4; kk++) {
            #pragma unroll
            for (int j = 0; j < 8; j++) {
                uint32_t bb[2];
                bb[0] = Ks[(j * 8 + g) * KSU + kk * 8 + c];
                bb[1] = Ks[(j * 8 + g) * KSU + kk * 8 + c + 4];
                mma_f16(sacc[0][j], Qr[0][kk], bb);
                mma_f16(sacc[1][j], Qr[1][kk], bb);
            }
        }

        // ---- masked online softmax (log2 domain; scale folded into Q) ----
        #pragma unroll
        for (int i = 0; i < 2; i++) {
            const int ra = q0 + wm + i * 16 + g;
            const int rb = ra + 8;
            #pragma unroll
            for (int j = 0; j < 8; j++) {
                const int col  = k0 + j * 8 + 2 * c;
                const float msk0 = Ms[j * 8 + 2 * c];
                const float msk1 = Ms[j * 8 + 2 * c + 1];
                float* s = sacc[i][j];
                s[0] = (col     <= ra) ? s[0] + msk0 : (NEGL + msk0);
                s[1] = (col + 1 <= ra) ? s[1] + msk1 : (NEGL + msk1);
                s[2] = (col     <= rb) ? s[2] + msk0 : (NEGL + msk0);
                s[3] = (col + 1 <= rb) ? s[3] + msk1 : (NEGL + msk1);
            }
            float mt0 = -1e30f, mt1 = -1e30f;
            #pragma unroll
            for (int j = 0; j < 8; j++) {
                mt0 = fmaxf(mt0, fmaxf(sacc[i][j][0], sacc[i][j][1]));
                mt1 = fmaxf(mt1, fmaxf(sacc[i][j][2], sacc[i][j][3]));
            }
            mt0 = fmaxf(mt0, __shfl_xor_sync(0xffffffffu, mt0, 1));
            mt0 = fmaxf(mt0, __shfl_xor_sync(0xffffffffu, mt0, 2));
            mt1 = fmaxf(mt1, __shfl_xor_sync(0xffffffffu, mt1, 1));
            mt1 = fmaxf(mt1, __shfl_xor_sync(0xffffffffu, mt1, 2));
            const float mn0 = fmaxf(mv[i][0], mt0), mn1 = fmaxf(mv[i][1], mt1);
            const float al0 = fexp2(mv[i][0] - mn0), al1 = fexp2(mv[i][1] - mn1);
            mv[i][0] = mn0; mv[i][1] = mn1;

            float ps0 = 0.f, ps1 = 0.f;
            const int pr = wm + i * 16 + g;
            #pragma unroll
            for (int j = 0; j < 8; j++) {
                float p0 = fexp2(sacc[i][j][0] - mn0);
                float p1 = fexp2(sacc[i][j][1] - mn0);
                float p2 = fexp2(sacc[i][j][2] - mn1);
                float p3 = fexp2(sacc[i][j][3] - mn1);
                __half2 hp0 = __floats2half2_rn(p0, p1);
                __half2 hp1 = __floats2half2_rn(p2, p3);
                float2 f0 = __half22float2(hp0);
                float2 f1 = __half22float2(hp1);
                ps0 += f0.x + f0.y;
                ps1 += f1.x + f1.y;
                Ps[pr * PSU + j * 4 + c]       = h2u(hp0);
                Ps[(pr + 8) * PSU + j * 4 + c] = h2u(hp1);
            }
            ps0 += __shfl_xor_sync(0xffffffffu, ps0, 1);
            ps0 += __shfl_xor_sync(0xffffffffu, ps0, 2);
            ps1 += __shfl_xor_sync(0xffffffffu, ps1, 1);
            ps1 += __shfl_xor_sync(0xffffffffu, ps1, 2);
            lv[i][0] = lv[i][0] * al0 + ps0;
            lv[i][1] = lv[i][1] * al1 + ps1;
            #pragma unroll
            for (int j = 0; j < 8; j++) {
                oacc[i][j][0] *= al0; oacc[i][j][1] *= al0;
                oacc[i][j][2] *= al1; oacc[i][j][3] *= al1;
            }
        }
        __syncwarp();

        // ---- O += P V ----
        #pragma unroll
        for (int kk = 0; kk < 4; kk++) {
            uint32_t pf[2][4];
            #pragma unroll
            for (int i = 0; i < 2; i++) {
                const int pr = wm + i * 16 + g;
                pf[i][0] = Ps[pr * PSU + kk * 8 + c];
                pf[i][1] = Ps[(pr + 8) * PSU + kk * 8 + c];
                pf[i][2] = Ps[pr * PSU + kk * 8 + c + 4];
                pf[i][3] = Ps[(pr + 8) * PSU + kk * 8 + c + 4];
            }
            #pragma unroll
            for (int j = 0; j < 8; j++) {
                uint32_t vf[2];
                vf[0] = Vs[(kk * 8 + c) * VSU + j * 8 + g];
                vf[1] = Vs[(kk * 8 + c + 4) * VSU + j * 8 + g];
                mma_f16(oacc[0][j], pf[0], vf);
                mma_f16(oacc[1][j], pf[1], vf);
            }
        }
    }

    // ---- Epilogue: normalize, pack fp16, write merged-head [B,S,D] ----
    uint32_t* Au = reinterpret_cast<uint32_t*>(g_ah);
    #pragma unroll
    for (int i = 0; i < 2; i++) {
        const float inv0 = 1.f / lv[i][0], inv1 = 1.f / lv[i][1];
        const int ra = q0 + wm + i * 16 + g;
        const size_t base0 = ((size_t)(b * SEQ + ra)) * 512 + h * 32;
        const size_t base1 = ((size_t)(b * SEQ + ra + 8)) * 512 + h * 32;
        #pragma unroll
        for (int j = 0; j < 8; j++) {
            Au[base0 + j * 4 + c] = h2u(__floats2half2_rn(oacc[i][j][0] * inv0, oacc[i][j][1] * inv0));
            Au[base1 + j * 4 + c] = h2u(__floats2half2_rn(oacc[i][j][2] * inv1, oacc[i][j][3] * inv1));
        }
    }
}

// ---------------------------------------------------------------------------
extern "C" void kernel_launch(void* const* d_in, const int* in_sizes, int n_in,
                              void* d_out, int out_size)
{
    const float* x      = (const float*)d_in[0];
    const float* amask  = (const float*)d_in[1];
    const float* W_attn = (const float*)d_in[2];
    const float* b_attn = (const float*)d_in[3];
    const float* W_proj = (const float*)d_in[4];
    const float* b_proj = (const float*)d_in[5];
    float* out = (float*)d_out;

    // 0) pack weights to fp16 (x conversion fused into GEMM1 staging)
    pack_wa_k<<<((DM / 2) * (3 * DM)) / 256, 256>>>(W_attn);
    pack_wp_k<<<((DM / 2) * DM) / 256, 256>>>(W_proj);

    // 1) QKV GEMM (fp16 m16n8k16, fp32 A converted in-kernel), head-split scatter
    dim3 g1(3072 / 128, MTOT / 128);
    gemm_h<MTOT, 3*DM, DM, 1, 0, 0><<<g1, 128>>>(x, b_attn, nullptr);

    // 2) Attention (fp16 m16n8k16, pipelined staging)
    attn_h<<<dim3(SEQ / 128, BH), 128>>>(amask);

    // 3) Output projection (fp16), fp32 output
    dim3 g2(DM / 128, MTOT / 128);
    gemm_h<MTOT, DM, DM, 0, 1, 1><<<g2, 128>>>(nullptr, b_proj, out);
}